// round 5
// baseline (speedup 1.0000x reference)
#include <cuda_runtime.h>
#include <math_constants.h>

// Banded sparse attention, B=256, S=128, D=1024, H=16, Dh=64, |i-j|<=4.
// No smem. 8-lane group handles 4 consecutive queries (12-row shared band).
// Weights stored DISTRIBUTED across group lanes (score (m,o) lives in lane
// o&7; o==8 slot in lane 0) to cut registers and raise occupancy.
// Dot reductions: 3-shfl allreduce. V-phase weight fetch: width-8 idx shfl.

#define SEQ    128
#define DMODEL 1024
#define NHEADS 16
#define HEADD  64
#define HW     4
#define BANDW  9
#define QPG    4              // queries per group
#define NT     (QPG + 2*HW)   // 12 band rows per group
#define QT     64             // queries per CTA
#define SCALE  0.125f

__device__ __forceinline__ float dot4(const float4 a, const float4 b) {
    return a.x * b.x + a.y * b.y + a.z * b.z + a.w * b.w;
}
__device__ __forceinline__ void fma4(float4& a, float w, const float4 v) {
    a.x += w * v.x; a.y += w * v.y; a.z += w * v.z; a.w += w * v.w;
}

__global__ __launch_bounds__(128, 6)
void banded_attn_kernel(const float* __restrict__ q,
                        const float* __restrict__ k,
                        const float* __restrict__ v,
                        float* __restrict__ out)
{
    const int b   = blockIdx.z;
    const int h   = blockIdx.y;
    const int q0  = blockIdx.x * QT;
    const int tid = threadIdx.x;

    const int g   = tid >> 3;          // group 0..15
    const int s   = tid & 7;           // lane in group; owns float4 cols 2s,2s+1
    const int i0  = q0 + g * QPG;      // first query of group
    const int j0g = i0 - HW;

    const size_t base = ((size_t)b * SEQ) * DMODEL + (size_t)h * HEADD;

    // ---- q rows (8 dims per lane per query) ----
    float4 qv[QPG][2];
#pragma unroll
    for (int m = 0; m < QPG; ++m) {
        const float4* qp = (const float4*)(q + base + (size_t)(i0 + m) * DMODEL);
        qv[m][0] = qp[2 * s];
        qv[m][1] = qp[2 * s + 1];
    }

    // Distributed weight slots: wa[m] holds score o==s; wb[m] (lane 0) o==8.
    float wa[QPG], wb[QPG];
#pragma unroll
    for (int m = 0; m < QPG; ++m) { wa[m] = -CUDART_INF_F; wb[m] = -CUDART_INF_F; }

    // ---- Scores over 12 shared k rows ----
    const float* kb = k + base;
#pragma unroll
    for (int t = 0; t < NT; ++t) {
        const int j = j0g + t;
        const bool valid = (j >= 0) && (j < SEQ);
        float4 k0 = make_float4(0.f, 0.f, 0.f, 0.f);
        float4 k1 = k0;
        if (valid) {
            const float4* kr = (const float4*)(kb + (size_t)j * DMODEL);
            k0 = kr[2 * s];
            k1 = kr[2 * s + 1];
        }
#pragma unroll
        for (int m = 0; m < QPG; ++m) {
            if (t >= m && t <= m + 2 * HW) {             // compile-time
                const int o = t - m;                      // band offset 0..8
                float d = dot4(qv[m][0], k0) + dot4(qv[m][1], k1);
                d += __shfl_xor_sync(0xffffffffu, d, 1);
                d += __shfl_xor_sync(0xffffffffu, d, 2);
                d += __shfl_xor_sync(0xffffffffu, d, 4);
                const float sc = valid ? d * SCALE : -CUDART_INF_F;
                if (o < 8) { if (s == o) wa[m] = sc; }
                else       { if (s == 0) wb[m] = sc; }
            }
        }
    }

    // ---- Softmax per query (distributed; 3-shfl max + 3-shfl sum) ----
#pragma unroll
    for (int m = 0; m < QPG; ++m) {
        float mloc = fmaxf(wa[m], (s == 0) ? wb[m] : -CUDART_INF_F);
        mloc = fmaxf(mloc, __shfl_xor_sync(0xffffffffu, mloc, 1));
        mloc = fmaxf(mloc, __shfl_xor_sync(0xffffffffu, mloc, 2));
        mloc = fmaxf(mloc, __shfl_xor_sync(0xffffffffu, mloc, 4));
        wa[m] = __expf(wa[m] - mloc);       // exp(-inf)=0 masks invalid slots
        wb[m] = __expf(wb[m] - mloc);
        float sloc = wa[m] + ((s == 0) ? wb[m] : 0.f);
        sloc += __shfl_xor_sync(0xffffffffu, sloc, 1);
        sloc += __shfl_xor_sync(0xffffffffu, sloc, 2);
        sloc += __shfl_xor_sync(0xffffffffu, sloc, 4);
        const float inv = 1.0f / sloc;
        wa[m] *= inv;
        wb[m] *= inv;
    }

    // ---- Weighted V over 12 shared v rows ----
    float4 acc[QPG][2];
#pragma unroll
    for (int m = 0; m < QPG; ++m) {
        acc[m][0] = make_float4(0.f, 0.f, 0.f, 0.f);
        acc[m][1] = acc[m][0];
    }
    const float* vb = v + base;
#pragma unroll
    for (int t = 0; t < NT; ++t) {
        const int j = j0g + t;
        float4 v0 = make_float4(0.f, 0.f, 0.f, 0.f);
        float4 v1 = v0;
        if (j >= 0 && j < SEQ) {
            const float4* vr = (const float4*)(vb + (size_t)j * DMODEL);
            v0 = vr[2 * s];
            v1 = vr[2 * s + 1];
        }
#pragma unroll
        for (int m = 0; m < QPG; ++m) {
            if (t >= m && t <= m + 2 * HW) {             // compile-time
                const int o = t - m;
                const float wm = (o < 8)
                    ? __shfl_sync(0xffffffffu, wa[m], o, 8)
                    : __shfl_sync(0xffffffffu, wb[m], 0, 8);
                fma4(acc[m][0], wm, v0);
                fma4(acc[m][1], wm, v1);
            }
        }
    }

    // ---- Store ----
#pragma unroll
    for (int m = 0; m < QPG; ++m) {
        float4* op = (float4*)(out + base + (size_t)(i0 + m) * DMODEL);
        op[2 * s]     = acc[m][0];
        op[2 * s + 1] = acc[m][1];
    }
}

extern "C" void kernel_launch(void* const* d_in, const int* in_sizes, int n_in,
                              void* d_out, int out_size)
{
    const float* q = (const float*)d_in[0];
    const float* k = (const float*)d_in[1];
    const float* v = (const float*)d_in[2];
    float* out = (float*)d_out;

    dim3 grid(SEQ / QT, NHEADS, 256);   // (2, 16, 256)
    dim3 block(128);                    // 16 groups x 4 queries
    banded_attn_kernel<<<grid, block>>>(q, k, v, out);
}

// round 7
// speedup vs baseline: 1.0437x; 1.0437x over previous
#include <cuda_runtime.h>
#include <math_constants.h>

// Banded sparse attention, B=256, S=128, D=1024, H=16, Dh=64, |i-j|<=4.
// No smem. 8-lane group handles 4 consecutive queries (12-row shared band).
// Packed butterfly: 4 same-t partial scores reduced with 4 shfls total;
// lane m_of_s ends owning query m's full 9-weight vector -> local softmax.
// V-phase: one width-8 shfl broadcast per (t,m). 84 shfl/warp vs 108.

#define SEQ    128
#define DMODEL 1024
#define NHEADS 16
#define HEADD  64
#define HW     4
#define BANDW  9
#define QPG    4              // queries per group
#define NT     (QPG + 2*HW)   // 12 band rows per group
#define QT     64             // queries per CTA
#define SCALE  0.125f
#define FULLM  0xffffffffu

__device__ __forceinline__ float dot4(const float4 a, const float4 b) {
    return a.x * b.x + a.y * b.y + a.z * b.z + a.w * b.w;
}
__device__ __forceinline__ void fma4(float4& a, float w, const float4 v) {
    a.x += w * v.x; a.y += w * v.y; a.z += w * v.z; a.w += w * v.w;
}

__global__ __launch_bounds__(128, 7)
void banded_attn_kernel(const float* __restrict__ q,
                        const float* __restrict__ k,
                        const float* __restrict__ v,
                        float* __restrict__ out)
{
    const int b   = blockIdx.z;
    const int h   = blockIdx.y;
    const int q0  = blockIdx.x * QT;
    const int tid = threadIdx.x;

    const int g   = tid >> 3;          // group 0..15
    const int s   = tid & 7;           // lane in group; owns float4 cols 2s,2s+1
    const int i0  = q0 + g * QPG;      // first query of group
    const int j0g = i0 - HW;

    // lane -> owned query within group (from butterfly end-state)
    const int mos = ((s & 1) << 1) | ((s >> 1) & 1);

    const size_t base = ((size_t)b * SEQ) * DMODEL + (size_t)h * HEADD;

    // ---- q rows (8 dims per lane per query) ----
    float4 qv[QPG][2];
#pragma unroll
    for (int m = 0; m < QPG; ++m) {
        const float4* qp = (const float4*)(q + base + (size_t)(i0 + m) * DMODEL);
        qv[m][0] = qp[2 * s];
        qv[m][1] = qp[2 * s + 1];
    }

    // Per-lane weight vector for its owned query
    float w[BANDW];

    // ---- Scores over 12 shared k rows; packed 4-value butterfly reduce ----
    const float* kb = k + base;
#pragma unroll
    for (int t = 0; t < NT; ++t) {
        const int j = j0g + t;
        const bool valid = (j >= 0) && (j < SEQ);
        float4 k0 = make_float4(0.f, 0.f, 0.f, 0.f);
        float4 k1 = k0;
        if (valid) {
            const float4* kr = (const float4*)(kb + (size_t)j * DMODEL);
            k0 = kr[2 * s];
            k1 = kr[2 * s + 1];
        }

        float d0 = 0.f, d1 = 0.f, d2 = 0.f, d3 = 0.f;
        if (t >= 0 && t <= 0 + 2 * HW) d0 = dot4(qv[0][0], k0) + dot4(qv[0][1], k1);
        if (t >= 1 && t <= 1 + 2 * HW) d1 = dot4(qv[1][0], k0) + dot4(qv[1][1], k1);
        if (t >= 2 && t <= 2 + 2 * HW) d2 = dot4(qv[2][0], k0) + dot4(qv[2][1], k1);
        if (t >= 3 && t <= 3 + 2 * HW) d3 = dot4(qv[3][0], k0) + dot4(qv[3][1], k1);

        // Round 1 (xor 1): 2 shfls, swap-different-values trick.
        // even lanes end owning {q0,q1} pair-sums; odd lanes {q2,q3}.
        const bool odd = (s & 1);
        float a  = odd ? d0 : d2;
        float ta = __shfl_xor_sync(FULLM, a, 1);
        float bb = odd ? d1 : d3;
        float tb = __shfl_xor_sync(FULLM, bb, 1);
        float e0 = odd ? (d2 + ta) : (d0 + ta);
        float e1 = odd ? (d3 + tb) : (d1 + tb);
        // Round 2 (xor 2): 1 shfl. (s&2)==0 keeps e0-query, else e1-query.
        const bool hi = (s & 2);
        float c  = hi ? e0 : e1;
        float tc = __shfl_xor_sync(FULLM, c, 2);
        float f  = hi ? (e1 + tc) : (e0 + tc);
        // Round 3 (xor 4): 1 shfl. Fully reduced over 8 lanes.
        f += __shfl_xor_sync(FULLM, f, 4);

        const float sc = valid ? f * SCALE : -CUDART_INF_F;
        // Lane owning query mm stores at compile-time index t-mm.
#pragma unroll
        for (int mm = 0; mm < QPG; ++mm) {
            if (t >= mm && t <= mm + 2 * HW) {      // compile-time
                if (mos == mm) w[t - mm] = sc;       // predicated select
            }
        }
    }

    // ---- Softmax: fully lane-local over the owned query's 9 weights ----
    {
        float mx = -CUDART_INF_F;
#pragma unroll
        for (int o = 0; o < BANDW; ++o) mx = fmaxf(mx, w[o]);
        float sum = 0.f;
#pragma unroll
        for (int o = 0; o < BANDW; ++o) { w[o] = __expf(w[o] - mx); sum += w[o]; }
        const float inv = 1.0f / sum;
#pragma unroll
        for (int o = 0; o < BANDW; ++o) w[o] *= inv;
    }

    // ---- Weighted V over 12 shared v rows ----
    float4 acc[QPG][2];
#pragma unroll
    for (int m = 0; m < QPG; ++m) {
        acc[m][0] = make_float4(0.f, 0.f, 0.f, 0.f);
        acc[m][1] = acc[m][0];
    }
    const float* vb = v + base;
#pragma unroll
    for (int t = 0; t < NT; ++t) {
        const int j = j0g + t;
        float4 v0 = make_float4(0.f, 0.f, 0.f, 0.f);
        float4 v1 = v0;
        if (j >= 0 && j < SEQ) {
            const float4* vr = (const float4*)(vb + (size_t)j * DMODEL);
            v0 = vr[2 * s];
            v1 = vr[2 * s + 1];
        }
#pragma unroll
        for (int mm = 0; mm < QPG; ++mm) {
            if (t >= mm && t <= mm + 2 * HW) {      // compile-time
                // weight owner lane for query mm (compile-time constant)
                const int src = ((mm >> 1) & 1) | ((mm & 1) << 1);
                const float wm = __shfl_sync(FULLM, w[t - mm], src, 8);
                fma4(acc[mm][0], wm, v0);
                fma4(acc[mm][1], wm, v1);
            }
        }
    }

    // ---- Store ----
#pragma unroll
    for (int m = 0; m < QPG; ++m) {
        float4* op = (float4*)(out + base + (size_t)(i0 + m) * DMODEL);
        op[2 * s]     = acc[m][0];
        op[2 * s + 1] = acc[m][1];
    }
}

extern "C" void kernel_launch(void* const* d_in, const int* in_sizes, int n_in,
                              void* d_out, int out_size)
{
    const float* q = (const float*)d_in[0];
    const float* k = (const float*)d_in[1];
    const float* v = (const float*)d_in[2];
    float* out = (float*)d_out;

    dim3 grid(SEQ / QT, NHEADS, 256);   // (2, 16, 256)
    dim3 block(128);                    // 16 groups x 4 queries
    banded_attn_kernel<<<grid, block>>>(q, k, v, out);
}